// round 10
// baseline (speedup 1.0000x reference)
#include <cuda_runtime.h>
#include <math.h>

#define B   1024
#define FR  257
#define C   32
#define L   4
#define TF  65
#define CHUNKS 4              // ceil(257/65); vrows = 65,65,65,62 (balanced)
#define NB  (B*CHUNKS)        // 4096 blocks in main kernel
#define NROW (B*FR)           // 263168 rows
#define NEG_BIG (-3.0e38f)

typedef unsigned long long u64;

// ---------------- scratch (static device globals; no allocation) ----------------
// Ping-pong pairs: layer l reads buf (l+1)&1, writes buf l&1 (race-free across
// the chunk-halo overlap; ordering via kernel launch boundaries).
__device__ __align__(16) float g_h[NROW*C];     // layer-0 input / final activations
__device__ __align__(16) float g_c0[NROW*C];    // conv output (pre-BN), buffer 0
__device__ __align__(16) float g_a0[NROW*C];    // attention output,     buffer 0
__device__ __align__(16) float g_c1[NROW*C];    // conv output (pre-BN), buffer 1
__device__ __align__(16) float g_a1[NROW*C];    // attention output,     buffer 1
__device__ __align__(16) float g_ps[NB*C];      // per-block BN partial sums
__device__ __align__(16) float g_pss[NB*C];     // per-block BN partial sum-of-squares
__device__ __align__(16) float g_stats[2*C];    // mean, inv_std per channel

__device__ __forceinline__ float gelu_f(float x){
    return 0.5f * x * (1.0f + erff(x * 0.70710678118654752f));
}

// ---- packed f32x2 helpers (Blackwell FFMA2: only reachable via PTX) ----
__device__ __forceinline__ u64 pack2(float lo, float hi){
    u64 u;
    asm("mov.b64 %0, {%1, %2};" : "=l"(u) : "f"(lo), "f"(hi));
    return u;
}
__device__ __forceinline__ void ffma2(u64 &acc, u64 a, u64 b){
    asm("fma.rn.f32x2 %0, %1, %2, %0;" : "+l"(acc) : "l"(a), "l"(b));
}
__device__ __forceinline__ float unpack_sum(u64 u){
    float lo, hi;
    asm("mov.b64 {%0, %1}, %2;" : "=f"(lo), "=f"(hi) : "l"(u));
    return lo + hi;
}

// fused BN+GELU+residual+LN for one float4 (8-lane row group; lane = tid&7)
__device__ __forceinline__ float4 fuse4(float4 cv, float4 av, int c4,
                                        const float* bg, const float* bb,
                                        const float* lg, const float* lb){
    float4 mean = ((const float4*)g_stats)[c4];
    float4 istd = ((const float4*)(g_stats+32))[c4];
    float4 bgv = ((const float4*)bg)[c4];
    float4 bbv = ((const float4*)bb)[c4];
    float4 lgv = ((const float4*)lg)[c4];
    float4 lbv = ((const float4*)lb)[c4];
    float4 y;
    y.x = gelu_f((cv.x - mean.x) * istd.x * bgv.x + bbv.x) + av.x;
    y.y = gelu_f((cv.y - mean.y) * istd.y * bgv.y + bbv.y) + av.y;
    y.z = gelu_f((cv.z - mean.z) * istd.z * bgv.z + bbv.z) + av.z;
    y.w = gelu_f((cv.w - mean.w) * istd.w * bgv.w + bbv.w) + av.w;
    float m = y.x + y.y + y.z + y.w;
    m += __shfl_xor_sync(0xffffffffu, m, 1);
    m += __shfl_xor_sync(0xffffffffu, m, 2);
    m += __shfl_xor_sync(0xffffffffu, m, 4);
    m *= 0.03125f;
    float4 d;
    d.x = y.x - m; d.y = y.y - m; d.z = y.z - m; d.w = y.w - m;
    float v = d.x*d.x + d.y*d.y + d.z*d.z + d.w*d.w;
    v += __shfl_xor_sync(0xffffffffu, v, 1);
    v += __shfl_xor_sync(0xffffffffu, v, 2);
    v += __shfl_xor_sync(0xffffffffu, v, 4);
    v *= 0.03125f;
    float is = rsqrtf(v + 1e-5f);
    float4 r;
    r.x = d.x * is * lgv.x + lbv.x;
    r.y = d.y * is * lgv.y + lbv.y;
    r.z = d.z * is * lgv.z + lbv.z;
    r.w = d.w * is * lgv.w + lbv.w;
    return r;
}

// ---------------- input projection: h = x(B,F,18) @ in_w(18,32) + in_b ----------
__global__ void k_inproj(const float* __restrict__ x,
                         const float* __restrict__ iw,
                         const float* __restrict__ ib){
    __shared__ __align__(16) float xr[144];     // 8 rows x 18, contiguous slice of x
    __shared__ float ws[18*32];
    int tid  = threadIdx.x;
    int row0 = blockIdx.x * 8;
    for (int i = tid; i < 18*32; i += 256) ws[i] = iw[i];
    if (tid < 36)
        ((float4*)xr)[tid] = ((const float4*)(x + row0*18))[tid];
    __syncthreads();
    int r = tid >> 5, o = tid & 31;
    const float* xrow = xr + r*18;
    float a0 = ib[o], a1 = 0.0f;
    #pragma unroll
    for (int k = 0; k < 9; k++)  a0 += xrow[k] * ws[k*32 + o];
    #pragma unroll
    for (int k = 9; k < 18; k++) a1 += xrow[k] * ws[k*32 + o];
    g_h[(row0 + r) * 32 + o] = a0 + a1;
}

// ---------------- main per-layer kernel: (fuse of prev layer) + conv + qkv + attn ----
// grid: (CHUNKS, B), block: 192 threads (6 warps), lane = output channel.
// mode 0: stage x from g_h (layer 0). mode 1/2: stage x = fuse(prev) from buf0/buf1.
// outsel 0/1: write conv/attn results to buf0/buf1.
__global__ __launch_bounds__(192, 2) void k_main(
    const float* __restrict__ cw,   // conv_w[l]  : (3,32,32)  tap,ci,co
    const float* __restrict__ qw,   // qkv_w[l]   : (32,96)
    const float* __restrict__ pw,   // proj_w[l]  : (32,32)
    const float* __restrict__ pb,   // proj_b[l]  : (32,)
    const float* __restrict__ pbg,  // prev layer bn_g
    const float* __restrict__ pbb,  // prev layer bn_b
    const float* __restrict__ plg,  // prev layer ln_g
    const float* __restrict__ plb,  // prev layer ln_b
    int mode, int outsel)
{
    __shared__ __align__(16) float xs[(TF+3)*32];   // frames f0-1 .. f0+TF+1
    __shared__ __align__(16) float qkvs[(TF+2)*96]; // frames f0   .. f0+TF+1
    __shared__ __align__(16) float atts[6][32];
    __shared__ float red[2][3][32];

    int tid = threadIdx.x;
    int w   = tid >> 5;     // warp id 0..5
    int o   = tid & 31;     // lane = channel
    int b     = blockIdx.y;
    int chunk = blockIdx.x;
    int f0    = chunk * TF;
    int base  = b * FR;
    int vrows = FR - f0; if (vrows > TF) vrows = TF;   // 65,65,65,62

    float* out_c = outsel ? g_c1 : g_c0;
    float* out_a = outsel ? g_a1 : g_a0;

    // stage x tile (zero outside [0,F)); layers>0 fuse prev layer on the fly
    {
        float4* xs4 = (float4*)xs;
        const float4 z4 = make_float4(0.f,0.f,0.f,0.f);
        if (mode == 0){
            const float4* h4 = (const float4*)g_h;
            for (int i = tid; i < (TF+3)*8; i += 192){
                int s = i >> 3, c4 = i & 7;
                int f = f0 - 1 + s;
                xs4[i] = (f >= 0 && f < FR) ? h4[(base + f)*8 + c4] : z4;
            }
        } else {
            const float4* cp = (const float4*)((mode == 1) ? g_c0 : g_c1);
            const float4* ap = (const float4*)((mode == 1) ? g_a0 : g_a1);
            for (int i = tid; i < (TF+3)*8; i += 192){
                int s = i >> 3, c4 = i & 7;
                int f = f0 - 1 + s;
                bool valid = (f >= 0 && f < FR);
                int gi = valid ? (base + f)*8 + c4 : 0;
                float4 cv = valid ? cp[gi] : z4;
                float4 av = valid ? ap[gi] : z4;
                // all lanes run fuse4 (shfl needs full 8-lane groups); invalid discarded
                float4 r = fuse4(cv, av, c4, pbg, pbb, plg, plb);
                xs4[i] = valid ? r : z4;
            }
        }
    }
    __syncthreads();

    // ---- phase 1: qkv (warps 0..2) / conv + BN partials (warps 3..5)
    if (w < 3) {
        int col = w*32 + o;                 // q: 0..31, k: 32..63, v: 64..95
        u64 wr2[16];                        // packed weight pairs (k even, k odd)
        #pragma unroll
        for (int k = 0; k < 16; k++)
            wr2[k] = pack2(qw[(2*k)*96 + col], qw[(2*k+1)*96 + col]);
        // q needs only valid rows; k,v need +2 halo (band lookahead).
        int rmax = (w == 0) ? vrows : vrows + 2;
        for (int r = 0; r < rmax; r++){
            const ulonglong2* x2 = (const ulonglong2*)(xs + (r+1)*32);
            u64 a0 = 0ull, a1 = 0ull;       // 2 packed accumulators (4-way ILP)
            #pragma unroll
            for (int kk = 0; kk < 8; kk++){
                ulonglong2 xv = x2[kk];     // LDS.128 -> two f32x2 operands
                ffma2(a0, xv.x, wr2[2*kk]);
                ffma2(a1, xv.y, wr2[2*kk+1]);
            }
            qkvs[r*96 + col] = unpack_sum(a0) + unpack_sum(a1);
        }
    } else {
        int t3 = w - 3;
        u64 wc2[3][16];                     // packed conv weight pairs per tap
        #pragma unroll
        for (int t = 0; t < 3; t++)
            #pragma unroll
            for (int k = 0; k < 16; k++)
                wc2[t][k] = pack2(cw[t*1024 + (2*k)*32 + o],
                                  cw[t*1024 + (2*k+1)*32 + o]);
        float sum = 0.0f, sumsq = 0.0f;
        for (int r = t3; r < vrows; r += 3){
            u64 ac[3] = {0ull, 0ull, 0ull}; // per-tap packed accumulators
            #pragma unroll
            for (int t = 0; t < 3; t++){
                const ulonglong2* x2 = (const ulonglong2*)(xs + (r+t)*32);
                #pragma unroll
                for (int kk = 0; kk < 8; kk++){
                    ulonglong2 xv = x2[kk];
                    ffma2(ac[t], xv.x, wc2[t][2*kk]);
                    ffma2(ac[t], xv.y, wc2[t][2*kk+1]);
                }
            }
            float cv = unpack_sum(ac[0]) + unpack_sum(ac[1]) + unpack_sum(ac[2]);
            out_c[(base + f0 + r)*32 + o] = cv;  // ping-pong: never the input buffer
            sum += cv; sumsq += cv*cv;
        }
        red[0][t3][o] = sum; red[1][t3][o] = sumsq;
    }
    __syncthreads();

    // warp 0: combine BN partials (3 conv warps), write per-block partials
    if (w == 0){
        float s  = red[0][0][o] + red[0][1][o] + red[0][2][o];
        float ss = red[1][0][o] + red[1][1][o] + red[1][2][o];
        int bid = b*CHUNKS + chunk;
        g_ps[bid*32 + o]  = s;
        g_pss[bid*32 + o] = ss;
    }

    // proj weights: loaded NOW (not phase 1) so conv warps' weight regs are dead
    u64 pwr2[16];
    #pragma unroll
    for (int k = 0; k < 16; k++)
        pwr2[k] = pack2(pw[(2*k)*32 + o], pw[(2*k+1)*32 + o]);

    // ---- phase 2: banded attention + proj (all 6 warps)
    const float pbr = pb[o];
    for (int r = w; r < vrows; r += 6){
        int i = f0 + r;
        // attention: window j in {0,1,2}, heads of 8 lanes
        float q = qkvs[r*96 + o];
        float sc[3];
        #pragma unroll
        for (int j = 0; j < 3; j++){
            float kk = qkvs[(r+j)*96 + 32 + o];
            float p = q * kk;
            p += __shfl_xor_sync(0xffffffffu, p, 1);
            p += __shfl_xor_sync(0xffffffffu, p, 2);
            p += __shfl_xor_sync(0xffffffffu, p, 4);
            sc[j] = (i + j < FR) ? p * 0.3535533905932738f : NEG_BIG;
        }
        float m = fmaxf(sc[0], fmaxf(sc[1], sc[2]));
        float att = 0.0f, den = 0.0f;
        #pragma unroll
        for (int j = 0; j < 3; j++){
            float e = __expf(sc[j] - m);     // softmax ratio: fast exp is safe
            den += e;
            att += e * qkvs[(r+j)*96 + 64 + o];
        }
        att /= den;
        // proj via smem broadcast: stage att vector, read back packed
        atts[w][o] = att;
        __syncwarp();
        const ulonglong2* a2 = (const ulonglong2*)(atts[w]);
        u64 p0 = pack2(pbr, 0.0f), p1 = 0ull;
        #pragma unroll
        for (int kk = 0; kk < 8; kk++){
            ulonglong2 av = a2[kk];
            ffma2(p0, av.x, pwr2[2*kk]);
            ffma2(p1, av.y, pwr2[2*kk+1]);
        }
        __syncwarp();
        out_a[(base + i)*32 + o] = unpack_sum(p0) + unpack_sum(p1);
    }
}

// ---------------- BN stats reduce: mean / inv_std per channel --------------------
__global__ void k_stats(){
    __shared__ float4 sps[1024];
    __shared__ float4 spss[1024];
    int t  = threadIdx.x;
    int c4 = t & 7;
    const float4* ps4  = (const float4*)g_ps;
    const float4* pss4 = (const float4*)g_pss;
    float4 s  = make_float4(0.f,0.f,0.f,0.f);
    float4 ss = make_float4(0.f,0.f,0.f,0.f);
    for (int r = t >> 3; r < NB; r += 128){
        float4 a = ps4[r*8 + c4];
        float4 bq = pss4[r*8 + c4];
        s.x += a.x;  s.y += a.y;  s.z += a.z;  s.w += a.w;
        ss.x += bq.x; ss.y += bq.y; ss.z += bq.z; ss.w += bq.w;
    }
    sps[t] = s; spss[t] = ss;
    __syncthreads();
    #pragma unroll
    for (int stp = 512; stp >= 8; stp >>= 1){
        if (t < stp){
            float4 a = sps[t+stp];
            sps[t].x += a.x; sps[t].y += a.y; sps[t].z += a.z; sps[t].w += a.w;
            float4 bq = spss[t+stp];
            spss[t].x += bq.x; spss[t].y += bq.y; spss[t].z += bq.z; spss[t].w += bq.w;
        }
        __syncthreads();
    }
    if (t < 8){
        float4 S = sps[t], SS = spss[t];
        const float inv = 1.0f / (float)NROW;
        float mx = S.x*inv, my = S.y*inv, mz = S.z*inv, mw = S.w*inv;
        g_stats[4*t+0] = mx;  g_stats[32 + 4*t+0] = rsqrtf(SS.x*inv - mx*mx + 1e-5f);
        g_stats[4*t+1] = my;  g_stats[32 + 4*t+1] = rsqrtf(SS.y*inv - my*my + 1e-5f);
        g_stats[4*t+2] = mz;  g_stats[32 + 4*t+2] = rsqrtf(SS.z*inv - mz*mz + 1e-5f);
        g_stats[4*t+3] = mw;  g_stats[32 + 4*t+3] = rsqrtf(SS.w*inv - mw*mw + 1e-5f);
    }
}

// ---------------- final fuse (layer 3 only): materialize g_h for the head -------
// Layer 3 writes buffer 1 (outsel = 3&1 = 1), so read g_c1/g_a1.
__global__ void k_fuse(const float* __restrict__ bg, const float* __restrict__ bb,
                       const float* __restrict__ lg, const float* __restrict__ lb){
    int tid = threadIdx.x;
    int c4  = tid & 7;
    int gi4 = blockIdx.x*256 + tid;
    float4 cv = ((const float4*)g_c1)[gi4];
    float4 av = ((const float4*)g_a1)[gi4];
    ((float4*)g_h)[gi4] = fuse4(cv, av, c4, bg, bb, lg, lb);
}

// ---------------- output head: gelu(h@h1)+sigmoid( @h2 ) -------------------------
__global__ void k_head(const float* __restrict__ w1, const float* __restrict__ b1,
                       const float* __restrict__ w2, const float* __restrict__ b2,
                       float* __restrict__ out){
    __shared__ float hs[8][32];
    __shared__ float w1s[512];
    __shared__ float b1s[16], w2s[16];
    int tid  = threadIdx.x;
    int row0 = blockIdx.x * 8;
    for (int i = tid; i < 512; i += 256) w1s[i] = w1[i];
    if (tid < 16){ b1s[tid] = b1[tid]; w2s[tid] = w2[tid]; }
    hs[tid >> 5][tid & 31] = g_h[(row0 + (tid >> 5))*32 + (tid & 31)];
    __syncthreads();
    int r = tid >> 5, j = tid & 31;
    float t = 0.0f;
    if (j < 16){
        float s = b1s[j];
        #pragma unroll
        for (int k = 0; k < 32; k++) s += hs[r][k] * w1s[k*16 + j];
        s = gelu_f(s);
        t = s * w2s[j];
    }
    t += __shfl_xor_sync(0xffffffffu, t, 1);
    t += __shfl_xor_sync(0xffffffffu, t, 2);
    t += __shfl_xor_sync(0xffffffffu, t, 4);
    t += __shfl_xor_sync(0xffffffffu, t, 8);
    if (j == 0) out[row0 + r] = 1.0f / (1.0f + __expf(-(t + b2[0])));
}

// ---------------- launch ---------------------------------------------------------
extern "C" void kernel_launch(void* const* d_in, const int* in_sizes, int n_in,
                              void* d_out, int out_size){
    const float* x      = (const float*)d_in[0];
    const float* in_w   = (const float*)d_in[1];
    const float* in_b   = (const float*)d_in[2];
    const float* conv_w = (const float*)d_in[3];
    const float* bn_g   = (const float*)d_in[4];
    const float* bn_b   = (const float*)d_in[5];
    const float* qkv_w  = (const float*)d_in[6];
    const float* proj_w = (const float*)d_in[7];
    const float* proj_b = (const float*)d_in[8];
    const float* ln_g   = (const float*)d_in[9];
    const float* ln_b   = (const float*)d_in[10];
    const float* h1_w   = (const float*)d_in[11];
    const float* h1_b   = (const float*)d_in[12];
    const float* h2_w   = (const float*)d_in[13];
    const float* h2_b   = (const float*)d_in[14];
    float* out = (float*)d_out;

    k_inproj<<<NROW/8, 256>>>(x, in_w, in_b);
    for (int l = 0; l < L; l++){
        dim3 g(CHUNKS, B);
        int p = (l > 0) ? (l-1) : 0;            // prev-layer params (unused when mode 0)
        int mode   = (l == 0) ? 0 : ((l & 1) ? 1 : 2); // read: h, buf0, buf1, buf0
        int outsel = l & 1;                              // write: buf0,1,0,1
        k_main<<<g, 192>>>(conv_w + l*3072, qkv_w + l*3072,
                           proj_w + l*1024, proj_b + l*32,
                           bn_g + p*32, bn_b + p*32, ln_g + p*32, ln_b + p*32,
                           mode, outsel);
        k_stats<<<1, 1024>>>();
    }
    // final fuse for layer 3 (buffer 1), then head
    k_fuse<<<(NROW*8)/256, 256>>>(bn_g + 3*32, bn_b + 3*32, ln_g + 3*32, ln_b + 3*32);
    k_head<<<NROW/8, 256>>>(h1_w, h1_b, h2_w, h2_b, out);
}

// round 13
// speedup vs baseline: 1.1396x; 1.1396x over previous
#include <cuda_runtime.h>
#include <math.h>

#define B   1024
#define FR  257
#define C   32
#define L   4
#define TF  65
#define CHUNKS 4              // ceil(257/65); vrows = 65,65,65,62 (balanced)
#define NB  (B*CHUNKS)        // 4096 blocks in main kernel
#define NROW (B*FR)           // 263168 rows
#define NEG_BIG (-3.0e38f)

typedef unsigned long long u64;

// ---------------- scratch (static device globals; no allocation) ----------------
// Ping-pong pairs: layer l reads buf (l+1)&1, writes buf l&1 (race-free across
// the chunk-halo overlap; ordering via kernel launch boundaries).
__device__ __align__(16) float g_h[NROW*C];     // layer-0 input / final activations
__device__ __align__(16) float g_c0[NROW*C];    // conv output (pre-BN), buffer 0
__device__ __align__(16) float g_a0[NROW*C];    // attention output,     buffer 0
__device__ __align__(16) float g_c1[NROW*C];    // conv output (pre-BN), buffer 1
__device__ __align__(16) float g_a1[NROW*C];    // attention output,     buffer 1
__device__ __align__(16) float g_ps[NB*C];      // per-block BN partial sums
__device__ __align__(16) float g_pss[NB*C];     // per-block BN partial sum-of-squares
__device__ __align__(16) float g_stats[2*C];    // mean, inv_std per channel

__device__ __forceinline__ float gelu_f(float x){
    return 0.5f * x * (1.0f + erff(x * 0.70710678118654752f));
}

// ---- packed f32x2 helpers (Blackwell FFMA2: only reachable via PTX) ----
__device__ __forceinline__ u64 pack2(float lo, float hi){
    u64 u;
    asm("mov.b64 %0, {%1, %2};" : "=l"(u) : "f"(lo), "f"(hi));
    return u;
}
__device__ __forceinline__ void ffma2(u64 &acc, u64 a, u64 b){
    asm("fma.rn.f32x2 %0, %1, %2, %0;" : "+l"(acc) : "l"(a), "l"(b));
}
__device__ __forceinline__ float unpack_sum(u64 u){
    float lo, hi;
    asm("mov.b64 {%0, %1}, %2;" : "=f"(lo), "=f"(hi) : "l"(u));
    return lo + hi;
}

// fused BN+GELU+residual+LN for one float4 (8-lane row group; lane = tid&7)
__device__ __forceinline__ float4 fuse4(float4 cv, float4 av, int c4,
                                        const float* bg, const float* bb,
                                        const float* lg, const float* lb){
    float4 mean = ((const float4*)g_stats)[c4];
    float4 istd = ((const float4*)(g_stats+32))[c4];
    float4 bgv = ((const float4*)bg)[c4];
    float4 bbv = ((const float4*)bb)[c4];
    float4 lgv = ((const float4*)lg)[c4];
    float4 lbv = ((const float4*)lb)[c4];
    float4 y;
    y.x = gelu_f((cv.x - mean.x) * istd.x * bgv.x + bbv.x) + av.x;
    y.y = gelu_f((cv.y - mean.y) * istd.y * bgv.y + bbv.y) + av.y;
    y.z = gelu_f((cv.z - mean.z) * istd.z * bgv.z + bbv.z) + av.z;
    y.w = gelu_f((cv.w - mean.w) * istd.w * bgv.w + bbv.w) + av.w;
    float m = y.x + y.y + y.z + y.w;
    m += __shfl_xor_sync(0xffffffffu, m, 1);
    m += __shfl_xor_sync(0xffffffffu, m, 2);
    m += __shfl_xor_sync(0xffffffffu, m, 4);
    m *= 0.03125f;
    float4 d;
    d.x = y.x - m; d.y = y.y - m; d.z = y.z - m; d.w = y.w - m;
    float v = d.x*d.x + d.y*d.y + d.z*d.z + d.w*d.w;
    v += __shfl_xor_sync(0xffffffffu, v, 1);
    v += __shfl_xor_sync(0xffffffffu, v, 2);
    v += __shfl_xor_sync(0xffffffffu, v, 4);
    v *= 0.03125f;
    float is = rsqrtf(v + 1e-5f);
    float4 r;
    r.x = d.x * is * lgv.x + lbv.x;
    r.y = d.y * is * lgv.y + lbv.y;
    r.z = d.z * is * lgv.z + lbv.z;
    r.w = d.w * is * lgv.w + lbv.w;
    return r;
}

// ---------------- input projection: h = x(B,F,18) @ in_w(18,32) + in_b ----------
__global__ void k_inproj(const float* __restrict__ x,
                         const float* __restrict__ iw,
                         const float* __restrict__ ib){
    __shared__ __align__(16) float xr[144];     // 8 rows x 18, contiguous slice of x
    __shared__ float ws[18*32];
    int tid  = threadIdx.x;
    int row0 = blockIdx.x * 8;
    for (int i = tid; i < 18*32; i += 256) ws[i] = iw[i];
    if (tid < 36)
        ((float4*)xr)[tid] = ((const float4*)(x + row0*18))[tid];
    __syncthreads();
    int r = tid >> 5, o = tid & 31;
    const float* xrow = xr + r*18;
    float a0 = ib[o], a1 = 0.0f;
    #pragma unroll
    for (int k = 0; k < 9; k++)  a0 += xrow[k] * ws[k*32 + o];
    #pragma unroll
    for (int k = 9; k < 18; k++) a1 += xrow[k] * ws[k*32 + o];
    g_h[(row0 + r) * 32 + o] = a0 + a1;
}

// ---------------- main per-layer kernel: (fuse of prev layer) + conv + qkv + attn ----
// grid: (CHUNKS, B), block: 192 threads (6 warps).
// Phase 1: warps 0-2 compute q,k,v (3 cols/lane) for 1/3 of rows each;
//          warps 3-5 compute all 3 conv taps (3 cols/lane) over contiguous
//          descending bands with rolling carries -> one broadcast per row per warp.
// mode 0: stage x from g_h (layer 0). mode 1/2: stage x = fuse(prev) from buf0/buf1.
__global__ __launch_bounds__(192, 2) void k_main(
    const float* __restrict__ cw,   // conv_w[l]  : (3,32,32)  tap,ci,co
    const float* __restrict__ qw,   // qkv_w[l]   : (32,96)
    const float* __restrict__ pw,   // proj_w[l]  : (32,32)
    const float* __restrict__ pb,   // proj_b[l]  : (32,)
    const float* __restrict__ pbg,  // prev layer bn_g
    const float* __restrict__ pbb,  // prev layer bn_b
    const float* __restrict__ plg,  // prev layer ln_g
    const float* __restrict__ plb,  // prev layer ln_b
    int mode, int outsel)
{
    __shared__ __align__(16) float xs[(TF+3)*32];   // rows s=0..67 = frames f0-1..f0+66
    __shared__ __align__(16) float qkvs[(TF+2)*96]; // output rows 0..66
    __shared__ __align__(16) float atts[6][32];
    __shared__ float red[2][3][32];

    int tid = threadIdx.x;
    int w   = tid >> 5;     // warp id 0..5
    int o   = tid & 31;     // lane = channel
    int b     = blockIdx.y;
    int chunk = blockIdx.x;
    int f0    = chunk * TF;
    int base  = b * FR;
    int vrows = FR - f0; if (vrows > TF) vrows = TF;   // 65,65,65,62

    float* out_c = outsel ? g_c1 : g_c0;
    float* out_a = outsel ? g_a1 : g_a0;

    // stage x tile (zero outside [0,F)); layers>0 fuse prev layer on the fly
    {
        float4* xs4 = (float4*)xs;
        const float4 z4 = make_float4(0.f,0.f,0.f,0.f);
        if (mode == 0){
            const float4* h4 = (const float4*)g_h;
            for (int i = tid; i < (TF+3)*8; i += 192){
                int s = i >> 3, c4 = i & 7;
                int f = f0 - 1 + s;
                xs4[i] = (f >= 0 && f < FR) ? h4[(base + f)*8 + c4] : z4;
            }
        } else {
            const float4* cp = (const float4*)((mode == 1) ? g_c0 : g_c1);
            const float4* ap = (const float4*)((mode == 1) ? g_a0 : g_a1);
            for (int i = tid; i < (TF+3)*8; i += 192){
                int s = i >> 3, c4 = i & 7;
                int f = f0 - 1 + s;
                bool valid = (f >= 0 && f < FR);
                int gi = valid ? (base + f)*8 + c4 : 0;
                float4 cv = valid ? cp[gi] : z4;
                float4 av = valid ? ap[gi] : z4;
                // all lanes run fuse4 (shfl needs full 8-lane groups); invalid discarded
                float4 r = fuse4(cv, av, c4, pbg, pbb, plg, plb);
                xs4[i] = valid ? r : z4;
            }
        }
    }
    __syncthreads();

    // ---- phase 1 ----
    if (w < 3) {
        // q,k,v (3 columns per lane) for rows s = 1+w, step 3, up to 67.
        u64 wq2[16], wk2[16], wv2[16];
        #pragma unroll
        for (int k = 0; k < 16; k++){
            wq2[k] = pack2(qw[(2*k)*96 + o],      qw[(2*k+1)*96 + o]);
            wk2[k] = pack2(qw[(2*k)*96 + 32 + o], qw[(2*k+1)*96 + 32 + o]);
            wv2[k] = pack2(qw[(2*k)*96 + 64 + o], qw[(2*k+1)*96 + 64 + o]);
        }
        for (int s = 1 + w; s <= TF + 2; s += 3){
            const ulonglong2* x2 = (const ulonglong2*)(xs + s*32);
            u64 aq = 0ull, ak = 0ull, av = 0ull;
            #pragma unroll
            for (int kk = 0; kk < 8; kk++){
                ulonglong2 xv = x2[kk];     // one broadcast feeds 3 columns
                ffma2(aq, xv.x, wq2[2*kk]);  ffma2(aq, xv.y, wq2[2*kk+1]);
                ffma2(ak, xv.x, wk2[2*kk]);  ffma2(ak, xv.y, wk2[2*kk+1]);
                ffma2(av, xv.x, wv2[2*kk]);  ffma2(av, xv.y, wv2[2*kk+1]);
            }
            int r = s - 1;
            qkvs[r*96 + o]      = unpack_sum(aq);
            qkvs[r*96 + 32 + o] = unpack_sum(ak);
            qkvs[r*96 + 64 + o] = unpack_sum(av);
        }
    } else {
        // conv: all 3 taps per lane, contiguous descending band, rolling carries.
        int t3 = w - 3;
        u64 wt2[3][16];
        #pragma unroll
        for (int t = 0; t < 3; t++)
            #pragma unroll
            for (int k = 0; k < 16; k++)
                wt2[t][k] = pack2(cw[t*1024 + (2*k)*32 + o],
                                  cw[t*1024 + (2*k+1)*32 + o]);
        int h  = (vrows + 2) / 3;                  // ceil(vrows/3)
        int r0 = t3 * h;
        int r1 = r0 + h; if (r1 > vrows) r1 = vrows;
        float sum = 0.0f, sumsq = 0.0f;
        float c1 = 0.0f, c2a = 0.0f, c2b = 0.0f;   // P1[s+1], P2[s+1], P2[s+2]
        for (int s = r1 + 1; s >= r0; --s){
            const ulonglong2* x2 = (const ulonglong2*)(xs + s*32);
            u64 A0 = 0ull, A1 = 0ull, A2 = 0ull;
            #pragma unroll
            for (int kk = 0; kk < 8; kk++){
                ulonglong2 xv = x2[kk];     // one broadcast feeds all 3 taps
                ffma2(A0, xv.x, wt2[0][2*kk]);  ffma2(A0, xv.y, wt2[0][2*kk+1]);
                ffma2(A1, xv.x, wt2[1][2*kk]);  ffma2(A1, xv.y, wt2[1][2*kk+1]);
                ffma2(A2, xv.x, wt2[2][2*kk]);  ffma2(A2, xv.y, wt2[2][2*kk+1]);
            }
            float P0 = unpack_sum(A0);
            float P1 = unpack_sum(A1);
            float P2 = unpack_sum(A2);
            if (s < r1){                    // emit out[s] = P0[s]+P1[s+1]+P2[s+2]
                float cv = P0 + c1 + c2b;
                out_c[(base + f0 + s)*32 + o] = cv;
                sum += cv; sumsq += cv*cv;
            }
            c2b = c2a; c2a = P2; c1 = P1;
        }
        red[0][t3][o] = sum; red[1][t3][o] = sumsq;
    }
    __syncthreads();

    // warp 0: combine BN partials (3 conv warps), write per-block partials
    if (w == 0){
        float s  = red[0][0][o] + red[0][1][o] + red[0][2][o];
        float ss = red[1][0][o] + red[1][1][o] + red[1][2][o];
        int bid = b*CHUNKS + chunk;
        g_ps[bid*32 + o]  = s;
        g_pss[bid*32 + o] = ss;
    }

    // proj weights: loaded now so phase-1 weight registers are dead
    u64 pwr2[16];
    #pragma unroll
    for (int k = 0; k < 16; k++)
        pwr2[k] = pack2(pw[(2*k)*32 + o], pw[(2*k+1)*32 + o]);

    // ---- phase 2: banded attention + proj (all 6 warps)
    const float pbr = pb[o];
    for (int r = w; r < vrows; r += 6){
        int i = f0 + r;
        // attention: window j in {0,1,2}, heads of 8 lanes
        float q = qkvs[r*96 + o];
        float sc[3];
        #pragma unroll
        for (int j = 0; j < 3; j++){
            float kk = qkvs[(r+j)*96 + 32 + o];
            float p = q * kk;
            p += __shfl_xor_sync(0xffffffffu, p, 1);
            p += __shfl_xor_sync(0xffffffffu, p, 2);
            p += __shfl_xor_sync(0xffffffffu, p, 4);
            sc[j] = (i + j < FR) ? p * 0.3535533905932738f : NEG_BIG;
        }
        float m = fmaxf(sc[0], fmaxf(sc[1], sc[2]));
        float att = 0.0f, den = 0.0f;
        #pragma unroll
        for (int j = 0; j < 3; j++){
            float e = __expf(sc[j] - m);     // softmax ratio: fast exp is safe
            den += e;
            att += e * qkvs[(r+j)*96 + 64 + o];
        }
        att /= den;
        // proj via smem broadcast: stage att vector, read back packed
        atts[w][o] = att;
        __syncwarp();
        const ulonglong2* a2 = (const ulonglong2*)(atts[w]);
        u64 p0 = pack2(pbr, 0.0f), p1 = 0ull;
        #pragma unroll
        for (int kk = 0; kk < 8; kk++){
            ulonglong2 av = a2[kk];
            ffma2(p0, av.x, pwr2[2*kk]);
            ffma2(p1, av.y, pwr2[2*kk+1]);
        }
        __syncwarp();
        out_a[(base + i)*32 + o] = unpack_sum(p0) + unpack_sum(p1);
    }
}

// ---------------- BN stats reduce: mean / inv_std per channel --------------------
__global__ void k_stats(){
    __shared__ float4 sps[1024];
    __shared__ float4 spss[1024];
    int t  = threadIdx.x;
    int c4 = t & 7;
    const float4* ps4  = (const float4*)g_ps;
    const float4* pss4 = (const float4*)g_pss;
    float4 s  = make_float4(0.f,0.f,0.f,0.f);
    float4 ss = make_float4(0.f,0.f,0.f,0.f);
    for (int r = t >> 3; r < NB; r += 128){
        float4 a = ps4[r*8 + c4];
        float4 bq = pss4[r*8 + c4];
        s.x += a.x;  s.y += a.y;  s.z += a.z;  s.w += a.w;
        ss.x += bq.x; ss.y += bq.y; ss.z += bq.z; ss.w += bq.w;
    }
    sps[t] = s; spss[t] = ss;
    __syncthreads();
    #pragma unroll
    for (int stp = 512; stp >= 8; stp >>= 1){
        if (t < stp){
            float4 a = sps[t+stp];
            sps[t].x += a.x; sps[t].y += a.y; sps[t].z += a.z; sps[t].w += a.w;
            float4 bq = spss[t+stp];
            spss[t].x += bq.x; spss[t].y += bq.y; spss[t].z += bq.z; spss[t].w += bq.w;
        }
        __syncthreads();
    }
    if (t < 8){
        float4 S = sps[t], SS = spss[t];
        const float inv = 1.0f / (float)NROW;
        float mx = S.x*inv, my = S.y*inv, mz = S.z*inv, mw = S.w*inv;
        g_stats[4*t+0] = mx;  g_stats[32 + 4*t+0] = rsqrtf(SS.x*inv - mx*mx + 1e-5f);
        g_stats[4*t+1] = my;  g_stats[32 + 4*t+1] = rsqrtf(SS.y*inv - my*my + 1e-5f);
        g_stats[4*t+2] = mz;  g_stats[32 + 4*t+2] = rsqrtf(SS.z*inv - mz*mz + 1e-5f);
        g_stats[4*t+3] = mw;  g_stats[32 + 4*t+3] = rsqrtf(SS.w*inv - mw*mw + 1e-5f);
    }
}

// ---------------- final fuse (layer 3 only): materialize g_h for the head -------
// Layer 3 writes buffer 1 (outsel = 3&1 = 1), so read g_c1/g_a1.
__global__ void k_fuse(const float* __restrict__ bg, const float* __restrict__ bb,
                       const float* __restrict__ lg, const float* __restrict__ lb){
    int tid = threadIdx.x;
    int c4  = tid & 7;
    int gi4 = blockIdx.x*256 + tid;
    float4 cv = ((const float4*)g_c1)[gi4];
    float4 av = ((const float4*)g_a1)[gi4];
    ((float4*)g_h)[gi4] = fuse4(cv, av, c4, bg, bb, lg, lb);
}

// ---------------- output head: gelu(h@h1)+sigmoid( @h2 ) -------------------------
__global__ void k_head(const float* __restrict__ w1, const float* __restrict__ b1,
                       const float* __restrict__ w2, const float* __restrict__ b2,
                       float* __restrict__ out){
    __shared__ float hs[8][32];
    __shared__ float w1s[512];
    __shared__ float b1s[16], w2s[16];
    int tid  = threadIdx.x;
    int row0 = blockIdx.x * 8;
    for (int i = tid; i < 512; i += 256) w1s[i] = w1[i];
    if (tid < 16){ b1s[tid] = b1[tid]; w2s[tid] = w2[tid]; }
    hs[tid >> 5][tid & 31] = g_h[(row0 + (tid >> 5))*32 + (tid & 31)];
    __syncthreads();
    int r = tid >> 5, j = tid & 31;
    float t = 0.0f;
    if (j < 16){
        float s = b1s[j];
        #pragma unroll
        for (int k = 0; k < 32; k++) s += hs[r][k] * w1s[k*16 + j];
        s = gelu_f(s);
        t = s * w2s[j];
    }
    t += __shfl_xor_sync(0xffffffffu, t, 1);
    t += __shfl_xor_sync(0xffffffffu, t, 2);
    t += __shfl_xor_sync(0xffffffffu, t, 4);
    t += __shfl_xor_sync(0xffffffffu, t, 8);
    if (j == 0) out[row0 + r] = 1.0f / (1.0f + __expf(-(t + b2[0])));
}

// ---------------- launch ---------------------------------------------------------
extern "C" void kernel_launch(void* const* d_in, const int* in_sizes, int n_in,
                              void* d_out, int out_size){
    const float* x      = (const float*)d_in[0];
    const float* in_w   = (const float*)d_in[1];
    const float* in_b   = (const float*)d_in[2];
    const float* conv_w = (const float*)d_in[3];
    const float* bn_g   = (const float*)d_in[4];
    const float* bn_b   = (const float*)d_in[5];
    const float* qkv_w  = (const float*)d_in[6];
    const float* proj_w = (const float*)d_in[7];
    const float* proj_b = (const float*)d_in[8];
    const float* ln_g   = (const float*)d_in[9];
    const float* ln_b   = (const float*)d_in[10];
    const float* h1_w   = (const float*)d_in[11];
    const float* h1_b   = (const float*)d_in[12];
    const float* h2_w   = (const float*)d_in[13];
    const float* h2_b   = (const float*)d_in[14];
    float* out = (float*)d_out;

    k_inproj<<<NROW/8, 256>>>(x, in_w, in_b);
    for (int l = 0; l < L; l++){
        dim3 g(CHUNKS, B);
        int p = (l > 0) ? (l-1) : 0;            // prev-layer params (unused when mode 0)
        int mode   = (l == 0) ? 0 : ((l & 1) ? 1 : 2); // read: h, buf0, buf1, buf0
        int outsel = l & 1;                              // write: buf0,1,0,1
        k_main<<<g, 192>>>(conv_w + l*3072, qkv_w + l*3072,
                           proj_w + l*1024, proj_b + l*32,
                           bn_g + p*32, bn_b + p*32, ln_g + p*32, ln_b + p*32,
                           mode, outsel);
        k_stats<<<1, 1024>>>();
    }
    // final fuse for layer 3 (buffer 1), then head
    k_fuse<<<(NROW*8)/256, 256>>>(bn_g + 3*32, bn_b + 3*32, ln_g + 3*32, ln_b + 3*32);
    k_head<<<NROW/8, 256>>>(h1_w, h1_b, h2_w, h2_b, out);
}